// round 1
// baseline (speedup 1.0000x reference)
#include <cuda_runtime.h>
#include <math.h>

// SpectralEMA: state_t = a*|state_{t-1}|*unit(x_t) + (1-rho)*x_t
// => state_t = x_t * (a*m_{t-1} + omr*w_t)/w_t,  m_t = |a*m_{t-1} + omr*w_t|
// Only the magnitude m needs to be carried through the scan; the complex
// state is reconstructed from the last x.

#define UNR 4

template <bool REAL_A>
__device__ __forceinline__ void run_scan(
    const float* __restrict__ pr, const float* __restrict__ pim,
    int S, size_t stF,
    float ar, float ai, float omr, float m,
    float& zr_out, float& zi_out, float& rinv_out, float& lxr_out, float& lxi_out)
{
    float zr = 0.0f, zi = 0.0f, rinv = 1.0f, lxr = 0.0f, lxi = 0.0f;

    int nch = S / UNR;
    float cxr[UNR], cxi[UNR];
    if (nch > 0) {
#pragma unroll
        for (int k = 0; k < UNR; ++k) {
            cxr[k] = __ldcs(pr + (size_t)k * stF);
            cxi[k] = __ldcs(pim + (size_t)k * stF);
        }
        pr  += (size_t)UNR * stF;
        pim += (size_t)UNR * stF;
    }
#pragma unroll 1
    for (int j = 0; j < nch; ++j) {
        float nxr[UNR], nxi[UNR];
        if (j + 1 < nch) {
#pragma unroll
            for (int k = 0; k < UNR; ++k) {
                nxr[k] = __ldcs(pr + (size_t)k * stF);
                nxi[k] = __ldcs(pim + (size_t)k * stF);
            }
            pr  += (size_t)UNR * stF;
            pim += (size_t)UNR * stF;
        }
#pragma unroll
        for (int k = 0; k < UNR; ++k) {
            float xr = cxr[k], xi = cxi[k];
            float x2 = fmaf(xr, xr, xi * xi);
            x2 = fmaxf(x2, 1e-37f);
            float rv = rsqrtf(x2);       // MUFU.RSQ
            float w  = x2 * rv;          // |x|
            zr = fmaf(ar, m, omr * w);
            if (REAL_A) {
                zi = 0.0f;
                m  = zr;                 // zr >= 0 (rho>0, omr>0, m>=0, w>=0)
            } else {
                zi = ai * m;
                float z2 = fmaf(zr, zr, zi * zi);
                z2 = fmaxf(z2, 1e-37f);
                m = z2 * rsqrtf(z2);
            }
            rinv = rv; lxr = xr; lxi = xi;
        }
#pragma unroll
        for (int k = 0; k < UNR; ++k) { cxr[k] = nxr[k]; cxi[k] = nxi[k]; }
    }
    // tail (S not multiple of UNR)
    for (int s = nch * UNR; s < S; ++s) {
        float xr = __ldcs(pr), xi = __ldcs(pim);
        pr += stF; pim += stF;
        float x2 = fmaf(xr, xr, xi * xi);
        x2 = fmaxf(x2, 1e-37f);
        float rv = rsqrtf(x2);
        float w  = x2 * rv;
        zr = fmaf(ar, m, omr * w);
        if (REAL_A) {
            zi = 0.0f; m = zr;
        } else {
            zi = ai * m;
            float z2 = fmaf(zr, zr, zi * zi);
            z2 = fmaxf(z2, 1e-37f);
            m = z2 * rsqrtf(z2);
        }
        rinv = rv; lxr = xr; lxi = xi;
    }

    zr_out = zr; zi_out = zi; rinv_out = rinv; lxr_out = lxr; lxi_out = lxi;
}

__global__ __launch_bounds__(256)
void spectral_ema_kernel(
    const float* __restrict__ fr, const float* __restrict__ fi,
    const float* __restrict__ ir, const float* __restrict__ ii,
    const float* __restrict__ rho_logit, const float* __restrict__ theta_raw,
    float2* __restrict__ out, int S, int F)
{
    int f = blockIdx.x * blockDim.x + threadIdx.x;
    if (f >= F) return;
    int b = blockIdx.y;

    // per-feature decay params
    float rho = 1.0f / (1.0f + expf(-rho_logit[f]));
    float th  = 3.14159265358979323846f * tanhf(theta_raw[f]);
    float ss, sc;
    sincosf(th, &ss, &sc);
    float ar  = rho * sc;
    float ai  = rho * ss;
    float omr = 1.0f - rho;

    size_t bf = (size_t)b * (size_t)F + (size_t)f;

    // m0 = |init_state|
    float m;
    {
        float sr = ir[bf], si = ii[bf];
        float s2 = fmaf(sr, sr, si * si);
        s2 = fmaxf(s2, 1e-37f);
        m = s2 * rsqrtf(s2);
    }

    const float* pr  = fr + (size_t)b * (size_t)S * (size_t)F + (size_t)f;
    const float* pim = fi + (size_t)b * (size_t)S * (size_t)F + (size_t)f;

    float zr, zi, rinv, lxr, lxi;
    if (ai == 0.0f) {
        run_scan<true >(pr, pim, S, (size_t)F, ar, ai, omr, m, zr, zi, rinv, lxr, lxi);
    } else {
        run_scan<false>(pr, pim, S, (size_t)F, ar, ai, omr, m, zr, zi, rinv, lxr, lxi);
    }

    // final = x_last * (zr + i*zi) / w_last
    float outr = (zr * lxr - zi * lxi) * rinv;
    float outi = fmaf(zr, lxi, zi * lxr) * rinv;
    out[bf] = make_float2(outr, outi);
}

extern "C" void kernel_launch(void* const* d_in, const int* in_sizes, int n_in,
                              void* d_out, int out_size)
{
    const float* fr  = (const float*)d_in[0];   // fft_real  [B,S,F]
    const float* fi  = (const float*)d_in[1];   // fft_imag  [B,S,F]
    const float* ir  = (const float*)d_in[2];   // init_real [B,F]
    const float* ii  = (const float*)d_in[3];   // init_imag [B,F]
    const float* rl  = (const float*)d_in[4];   // rho_logit [F]
    const float* tr  = (const float*)d_in[5];   // theta_raw [F]

    int F  = in_sizes[4];
    int BF = in_sizes[2];
    int B  = BF / F;
    int S  = in_sizes[0] / BF;

    dim3 block(256);
    dim3 grid((F + 255) / 256, B);
    spectral_ema_kernel<<<grid, block>>>(fr, fi, ir, ii, rl, tr,
                                         (float2*)d_out, S, F);
}